// round 12
// baseline (speedup 1.0000x reference)
#include <cuda_runtime.h>
#include <math.h>

#define N_ADDR 150000
#define N_TX   200000
#define HID    32
#define HEADS  4
#define E_AT   1000000
#define E_TA   1000000
#define E_AA   500000
#define E_TOT  (E_AT + E_TA + E_AA)
#define NODES  (N_ADDR + N_TX)
#define W_TOT  (N_TX + 2 * N_ADDR)
#define PROJ_NPB 32

// ---------------- scratch (device globals; no allocations allowed) ----------------
__device__ __align__(16) float g_ha[(size_t)N_ADDR * HID];
__device__ __align__(16) float g_ht[(size_t)N_TX * HID];
__device__ __align__(16) float g_t [(size_t)N_TX * HID];

__device__ __align__(16) float g_oa1[(size_t)N_ADDR * HID];
__device__ __align__(16) float g_oa2[(size_t)N_ADDR * HID];

__device__ __align__(16) float g_asA0[(size_t)N_ADDR * HEADS];
__device__ __align__(16) float g_asA2[(size_t)N_ADDR * HEADS];
__device__ __align__(16) float g_adA1[(size_t)N_ADDR * HEADS];
__device__ __align__(16) float g_adA2[(size_t)N_ADDR * HEADS];
__device__ __align__(16) float g_asT [(size_t)N_TX * HEADS];
__device__ __align__(16) float g_adT [(size_t)N_TX * HEADS];

// CSR structures (built once per launch; topology shared by all 3 layers)
__device__ int g_cnt[3][N_TX];
__device__ int g_off[3][N_TX + 1];
__device__ int g_cur[3][N_TX];
__device__ int g_bsum[3][128];
__device__ int g_csr0[E_AT];
__device__ int g_csr1[E_TA];
__device__ int g_csr2[E_AA];

// zero-initialized at module load; k_attn re-zeroes after each use so every
// layer (and every graph replay) starts from zero.
__device__ unsigned g_gmax[3 * HEADS];
__device__ float g_sem[2 * HID];
__device__ float g_attn[2];

// ---------------- helpers ----------------
__device__ __forceinline__ unsigned fenc(float x) {
    unsigned b = __float_as_uint(x);
    return (b & 0x80000000u) ? ~b : (b | 0x80000000u);
}
__device__ __forceinline__ float fdec(unsigned u) {
    return (u & 0x80000000u) ? __uint_as_float(u & 0x7FFFFFFFu)
                             : __uint_as_float(~u);
}
__device__ __forceinline__ float lrelu(float l) { return l >= 0.f ? l : 0.2f * l; }
static inline int cdiv(int a, int b) { return (a + b - 1) / b; }

// ---------------- CSR build ----------------
__global__ void k_zero_cnt() {
    int i = blockIdx.x * blockDim.x + threadIdx.x;
    if (i < N_TX) g_cnt[0][i] = 0;
    if (i < N_ADDR) { g_cnt[1][i] = 0; g_cnt[2][i] = 0; }
}

__global__ void k_hist_all(const int* __restrict__ d0, const int* __restrict__ d1,
                           const int* __restrict__ d2) {
    int e = blockIdx.x * blockDim.x + threadIdx.x;
    if (e < E_AT) atomicAdd(&g_cnt[0][d0[e]], 1);
    else if (e < E_AT + E_TA) atomicAdd(&g_cnt[1][d1[e - E_AT]], 1);
    else if (e < E_TOT) atomicAdd(&g_cnt[2][d2[e - E_AT - E_TA]], 1);
}

// block-level exclusive scan: 1024 threads x 4 elements; blockIdx.y = relation
__global__ void k_scan1() {
    __shared__ int ws[32];
    int rel = blockIdx.y;
    int N = (rel == 0) ? N_TX : N_ADDR;
    const int* cnt = g_cnt[rel];
    int* off = g_off[rel];
    int t = threadIdx.x, lane = t & 31, wid = t >> 5;
    int base = blockIdx.x * 4096 + t * 4;
    int v0 = (base + 0 < N) ? cnt[base + 0] : 0;
    int v1 = (base + 1 < N) ? cnt[base + 1] : 0;
    int v2 = (base + 2 < N) ? cnt[base + 2] : 0;
    int v3 = (base + 3 < N) ? cnt[base + 3] : 0;
    int tsum = v0 + v1 + v2 + v3;
    int x = tsum;
    for (int o = 1; o < 32; o <<= 1) {
        int y = __shfl_up_sync(0xffffffffu, x, o);
        if (lane >= o) x += y;
    }
    if (lane == 31) ws[wid] = x;
    __syncthreads();
    if (wid == 0) {
        int w = ws[lane];
        for (int o = 1; o < 32; o <<= 1) {
            int y = __shfl_up_sync(0xffffffffu, w, o);
            if (lane >= o) w += y;
        }
        ws[lane] = w;
    }
    __syncthreads();
    int excl = x - tsum + (wid > 0 ? ws[wid - 1] : 0);
    if (base + 0 < N) off[base + 0] = excl;
    if (base + 1 < N) off[base + 1] = excl + v0;
    if (base + 2 < N) off[base + 2] = excl + v0 + v1;
    if (base + 3 < N) off[base + 3] = excl + v0 + v1 + v2;
    if (t == 1023) g_bsum[rel][blockIdx.x] = excl + tsum;
}

__global__ void k_scan2() {
    __shared__ int sh[128];
    int rel = blockIdx.y;
    const int nb = 49;
    int t = threadIdx.x;
    int orig = (t < nb) ? g_bsum[rel][t] : 0;
    sh[t] = orig;
    __syncthreads();
    for (int o = 1; o < 128; o <<= 1) {
        int v = (t >= o) ? sh[t - o] : 0;
        __syncthreads();
        sh[t] += v;
        __syncthreads();
    }
    if (t < nb) g_bsum[rel][t] = sh[t] - orig;
}

__global__ void k_scan3() {
    int rel = blockIdx.y;
    int N = (rel == 0) ? N_TX : N_ADDR;
    int i = blockIdx.x * blockDim.x + threadIdx.x;
    if (i >= N) return;
    int o = g_off[rel][i] + g_bsum[rel][i >> 12];
    g_off[rel][i] = o;
    g_cur[rel][i] = o;
    if (i == N - 1) g_off[rel][N] = o + g_cnt[rel][i];
}

// csr selected in device code (host-side __device__ symbol = wrong address)
__global__ void k_scatter_all(const int* __restrict__ s0, const int* __restrict__ d0,
                              const int* __restrict__ s1, const int* __restrict__ d1,
                              const int* __restrict__ s2, const int* __restrict__ d2) {
    int e = blockIdx.x * blockDim.x + threadIdx.x;
    if (e < E_AT) {
        int p = atomicAdd(&g_cur[0][d0[e]], 1);
        g_csr0[p] = s0[e];
    } else if (e < E_AT + E_TA) {
        int i = e - E_AT;
        int p = atomicAdd(&g_cur[1][d1[i]], 1);
        g_csr1[p] = s1[i];
    } else if (e < E_TOT) {
        int i = e - E_AT - E_TA;
        int p = atomicAdd(&g_cur[2][d2[i]], 1);
        g_csr2[p] = s2[i];
    }
}

// ---------------- per-layer kernels ----------------

// fused: [semantic mix of previous layer (l>0)] + projection (both node types)
// + attention dot products + global alpha_src max (fused k_amax).
// one 32-node tile per block (R8 occupancy point; persistent grid regressed).
// 4 nodes/warp, 8 lanes/node, lane owns a float4 of output channels.
__global__ void k_proj_all(const float* __restrict__ xa, const float* __restrict__ xt,
                           int useExt,
                           const float* __restrict__ Wa, const float* __restrict__ ba,
                           const float* __restrict__ Wt, const float* __restrict__ bt,
                           const float* __restrict__ asl, const float* __restrict__ adl,
                           int F4, int f4sh) {
    __shared__ float4 sWa[64 * 8], sWt[64 * 8];
    __shared__ float4 sx[PROJ_NPB * 17];
    __shared__ float4 sba4[8], sbt4[8], sv4[6][8];
    __shared__ unsigned smax[12];
    int tid = threadIdx.x;
    int Wn = (F4 << 2) * 8;
    for (int i = tid; i < Wn; i += blockDim.x) {
        sWa[i] = ((const float4*)Wa)[i];
        sWt[i] = ((const float4*)Wt)[i];
    }
    if (tid < 8) {
        sba4[tid] = ((const float4*)ba)[tid];
        sbt4[tid] = ((const float4*)bt)[tid];
    }
    if (tid < 48) {
        int r = tid >> 3, cc = tid & 7;
        const float* p = (r == 0) ? asl : (r == 1) ? asl + 64 :
                         (r == 2) ? adl + 32 : (r == 3) ? adl + 64 :
                         (r == 4) ? asl + 32 : adl;
        sv4[r][cc] = ((const float4*)p)[cc];
    }
    if (tid < 12) smax[tid] = 0u;

    float a0 = 0.f, a1 = 0.f;
    if (!useExt) { a0 = g_attn[0]; a1 = g_attn[1]; }

    int nbase = blockIdx.x * PROJ_NPB;
    int items = PROJ_NPB << f4sh;
    for (int i = tid; i < items; i += blockDim.x) {
        int row = i >> f4sh, k4 = i & (F4 - 1);
        int node = nbase + row;
        if (node < NODES) {
            bool iA = node < N_ADDR;
            int n = iA ? node : node - N_ADDR;
            float4 v;
            if (useExt) {
                v = ((const float4*)(iA ? xa : xt))[((size_t)n << f4sh) + k4];
            } else if (iA) {
                float4 u = ((const float4*)g_oa1)[(size_t)n * 8 + k4];
                float4 w = ((const float4*)g_oa2)[(size_t)n * 8 + k4];
                v = make_float4(fmaxf(a0 * u.x + a1 * w.x, 0.f),
                                fmaxf(a0 * u.y + a1 * w.y, 0.f),
                                fmaxf(a0 * u.z + a1 * w.z, 0.f),
                                fmaxf(a0 * u.w + a1 * w.w, 0.f));
            } else {
                v = ((const float4*)g_t)[(size_t)n * 8 + k4];
            }
            sx[row * 17 + k4] = v;
        }
    }
    __syncthreads();

    int lane = tid & 31;
    int g = lane >> 3, c4 = lane & 7;
    int lrow = (tid >> 5) * 4 + g;
    int node = nbase + lrow;

    float lm0 = -1e30f, lm1 = -1e30f, lm2 = -1e30f;
    if (node < NODES) {
        bool isA = node < N_ADDR;
        int n = isA ? node : node - N_ADDR;
        const float4* sW = isA ? sWa : sWt;
        float4 acc = isA ? sba4[c4] : sbt4[c4];
        const float4* xr = sx + lrow * 17;
        for (int k4 = 0; k4 < F4; k4++) {
            float4 xv = xr[k4];
            float4 w0 = sW[(4 * k4 + 0) * 8 + c4];
            float4 w1 = sW[(4 * k4 + 1) * 8 + c4];
            float4 w2 = sW[(4 * k4 + 2) * 8 + c4];
            float4 w3 = sW[(4 * k4 + 3) * 8 + c4];
            acc.x += xv.x * w0.x + xv.y * w1.x + xv.z * w2.x + xv.w * w3.x;
            acc.y += xv.x * w0.y + xv.y * w1.y + xv.z * w2.y + xv.w * w3.y;
            acc.z += xv.x * w0.z + xv.y * w1.z + xv.z * w2.z + xv.w * w3.z;
            acc.w += xv.x * w0.w + xv.y * w1.w + xv.z * w2.w + xv.w * w3.w;
        }
        ((float4*)((isA ? g_ha : g_ht) + (size_t)n * HID))[c4] = acc;

        float4 s0 = sv4[isA ? 0 : 4][c4];
        float4 s1 = sv4[isA ? 1 : 5][c4];
        float p0 = acc.x * s0.x + acc.y * s0.y + acc.z * s0.z + acc.w * s0.w;
        float p1 = acc.x * s1.x + acc.y * s1.y + acc.z * s1.z + acc.w * s1.w;
        float p2 = 0.f, p3 = 0.f;
        if (isA) {
            float4 s2 = sv4[2][c4], s3 = sv4[3][c4];
            p2 = acc.x * s2.x + acc.y * s2.y + acc.z * s2.z + acc.w * s2.w;
            p3 = acc.x * s3.x + acc.y * s3.y + acc.z * s3.z + acc.w * s3.w;
        }
        p0 += __shfl_xor_sync(0xffffffffu, p0, 1);
        p1 += __shfl_xor_sync(0xffffffffu, p1, 1);
        p2 += __shfl_xor_sync(0xffffffffu, p2, 1);
        p3 += __shfl_xor_sync(0xffffffffu, p3, 1);
        if ((c4 & 1) == 0) {
            int h = c4 >> 1;
            if (isA) {
                g_asA0[(size_t)n * 4 + h] = p0;
                g_asA2[(size_t)n * 4 + h] = p1;
                g_adA1[(size_t)n * 4 + h] = p2;
                g_adA2[(size_t)n * 4 + h] = p3;
                lm0 = p0; lm2 = p1;
            } else {
                g_asT[(size_t)n * 4 + h] = p0;
                g_adT[(size_t)n * 4 + h] = p1;
                lm1 = p0;
            }
        }
    }

    // reduce alpha_src maxes: smem atomics, then <=12 global atomics per block
    if ((c4 & 1) == 0) {
        int h = c4 >> 1;
        if (lm0 > -1e30f) atomicMax(&smax[0 * 4 + h], fenc(lm0));
        if (lm1 > -1e30f) atomicMax(&smax[1 * 4 + h], fenc(lm1));
        if (lm2 > -1e30f) atomicMax(&smax[2 * 4 + h], fenc(lm2));
    }
    __syncthreads();
    if (tid < 12 && smax[tid] != 0u) atomicMax(&g_gmax[tid], smax[tid]);
}

// fused gather aggregation, all 3 relations. 4 nodes/warp, 8 lanes/node;
// lane owns one float4 of channels. Inner loop STATICALLY unrolled (8) with
// predication so the per-edge alpha/feature loads issue independently (MLP~8)
// instead of a serial dependent chain.
__global__ void k_agg_all() {
    int warp = blockIdx.x * (blockDim.x >> 5) + (threadIdx.x >> 5);
    int lane = threadIdx.x & 31;
    int g = lane >> 3, c4 = lane & 7, h = c4 >> 1;
    int vn = warp * 4 + g;
    if (vn >= W_TOT) return;
    int rel, node;
    if (vn < N_TX) { rel = 0; node = vn; }
    else if (vn < N_TX + N_ADDR) { rel = 1; node = vn - N_TX; }
    else { rel = 2; node = vn - N_TX - N_ADDR; }

    const int* off; const int* csr; const float* as_; const float* ad_;
    const float* hs; float* outp;
    if (rel == 0)      { off = g_off[0]; csr = g_csr0; as_ = g_asA0; ad_ = g_adT;  hs = g_ha; outp = g_t; }
    else if (rel == 1) { off = g_off[1]; csr = g_csr1; as_ = g_asT;  ad_ = g_adA1; hs = g_ht; outp = g_oa1; }
    else               { off = g_off[2]; csr = g_csr2; as_ = g_asA2; ad_ = g_adA2; hs = g_ha; outp = g_oa2; }

    int start = off[node], end = off[node + 1];
    float4 res = make_float4(0.f, 0.f, 0.f, 0.f);
    if (start < end) {
        float adv = ad_[(size_t)node * 4 + h];
        float m = lrelu(fdec(g_gmax[rel * 4 + h]) + adv);  // >= all edge logits
        unsigned gm = 0xFFu << (g * 8);
        float4 acc = make_float4(0.f, 0.f, 0.f, 0.f);
        float ssum = 0.f;
        for (int base = start; base < end; base += 8) {
            int idx = (c4 < end - base) ? csr[base + c4] : 0;
#pragma unroll
            for (int j = 0; j < 8; j++) {
                int s = __shfl_sync(gm, idx, g * 8 + j);
                if (base + j < end) {
                    float a = as_[(size_t)s * 4 + h];
                    float w = __expf(lrelu(a + adv) - m);
                    float4 f = ((const float4*)(hs + (size_t)s * HID))[c4];
                    acc.x += w * f.x; acc.y += w * f.y;
                    acc.z += w * f.z; acc.w += w * f.w;
                    ssum += w;
                }
            }
        }
        float inv = 1.f / (ssum + 1e-16f);
        res = make_float4(fmaxf(acc.x * inv, 0.f), fmaxf(acc.y * inv, 0.f),
                          fmaxf(acc.z * inv, 0.f), fmaxf(acc.w * inv, 0.f));
    }
    ((float4*)(outp + (size_t)node * HID))[c4] = res;
}

// semantic accumulation: warp per node (coalesced), lane = channel.
__global__ void k_semacc(const float* __restrict__ kWl, const float* __restrict__ kbl) {
    int r = blockIdx.y;
    const float* O = (r == 0) ? (const float*)g_oa1 : (const float*)g_oa2;
    __shared__ float sW[HID * HID];
    __shared__ float sb_[HID];
    __shared__ float red[HID];
    int tid = threadIdx.x, lane = tid & 31, wid = tid >> 5;
    for (int i = tid; i < HID * HID; i += blockDim.x) sW[i] = kWl[i];
    if (tid < HID) { sb_[tid] = kbl[tid]; red[tid] = 0.f; }
    __syncthreads();

    float acc = 0.f;
    int wstride = gridDim.x * (blockDim.x >> 5);
    for (int n = blockIdx.x * (blockDim.x >> 5) + wid; n < N_ADDR; n += wstride) {
        float x = O[(size_t)n * HID + lane];
        float dsum = sb_[lane];
#pragma unroll
        for (int k = 0; k < HID; k++)
            dsum += __shfl_sync(0xffffffffu, x, k) * sW[k * HID + lane];
        acc += tanhf(dsum);
    }
    atomicAdd(&red[lane], acc);
    __syncthreads();
    if (tid < HID) atomicAdd(&g_sem[r * HID + tid], red[tid]);
}

// softmax over 2 relation scores; resets g_sem/g_gmax for next layer/replay
__global__ void k_attn(const float* __restrict__ q) {
    int c = threadIdx.x;
    const float inv = 1.0f / (float)N_ADDR;
    float qc = q[c];
    float p0 = g_sem[c] * inv * qc;
    float p1 = g_sem[HID + c] * inv * qc;
    for (int o = 16; o > 0; o >>= 1) {
        p0 += __shfl_xor_sync(0xffffffffu, p0, o);
        p1 += __shfl_xor_sync(0xffffffffu, p1, o);
    }
    if (c == 0) {
        float m = fmaxf(p0, p1);
        float e0 = __expf(p0 - m), e1 = __expf(p1 - m);
        float is = 1.f / (e0 + e1);
        g_attn[0] = e0 * is;
        g_attn[1] = e1 * is;
    }
    __syncwarp();
    g_sem[c] = 0.f;
    g_sem[HID + c] = 0.f;
    if (c < 3 * HEADS) g_gmax[c] = 0u;
}

// final linear with fused semantic mix: warp per node, shfl reduce.
__global__ void k_lin(const float* __restrict__ linW, const float* __restrict__ linb,
                      float* __restrict__ out) {
    int gw = blockIdx.x * (blockDim.x >> 5) + (threadIdx.x >> 5);
    int c = threadIdx.x & 31;
    if (gw >= N_ADDR) return;
    float a0 = g_attn[0], a1 = g_attn[1];
    float v = fmaxf(a0 * g_oa1[(size_t)gw * HID + c] +
                    a1 * g_oa2[(size_t)gw * HID + c], 0.f);
    float s0 = v * linW[c * 2];
    float s1 = v * linW[c * 2 + 1];
#pragma unroll
    for (int o = 16; o > 0; o >>= 1) {
        s0 += __shfl_xor_sync(0xffffffffu, s0, o);
        s1 += __shfl_xor_sync(0xffffffffu, s1, o);
    }
    if (c == 0)
        *(float2*)(out + (size_t)gw * 2) = make_float2(s0 + linb[0], s1 + linb[1]);
}

// ---------------- host ----------------
extern "C" void kernel_launch(void* const* d_in, const int* in_sizes, int n_in,
                              void* d_out, int out_size) {
    const float* x_addr  = (const float*)d_in[0];
    const float* x_tx    = (const float*)d_in[1];
    const int*   eat_s   = (const int*)d_in[2];
    const int*   eat_d   = (const int*)d_in[3];
    const int*   eta_s   = (const int*)d_in[4];
    const int*   eta_d   = (const int*)d_in[5];
    const int*   eaa_s   = (const int*)d_in[6];
    const int*   eaa_d   = (const int*)d_in[7];
    const float* pW1     = (const float*)d_in[8];
    const float* pb1     = (const float*)d_in[9];
    const float* pW23    = (const float*)d_in[10];
    const float* pb23    = (const float*)d_in[11];
    const float* att_src = (const float*)d_in[12];
    const float* att_dst = (const float*)d_in[13];
    const float* kW      = (const float*)d_in[14];
    const float* kb      = (const float*)d_in[15];
    const float* q       = (const float*)d_in[16];
    const float* linW    = (const float*)d_in[17];
    const float* linb    = (const float*)d_in[18];
    float* out = (float*)d_out;

    const int B = 256;
    const int PROJ_BLK = cdiv(NODES, PROJ_NPB);
    const int AGG_BLK = cdiv(W_TOT / 4, 8);   // 4 nodes/warp, 8 warps/block

    // ---- CSR build (once); layer-0 proj interleaved (independent) ----
    k_zero_cnt<<<cdiv(N_TX, B), B>>>();
    k_hist_all<<<cdiv(E_TOT, B), B>>>(eat_d, eta_d, eaa_d);
    k_scan1<<<dim3(49, 3), 1024>>>();
    k_proj_all<<<PROJ_BLK, B>>>(x_addr, x_tx, 1,
                                pW1, pb1, pW1 + 64 * HID, pb1 + HID,
                                att_src, att_dst, 16, 4);
    k_scan2<<<dim3(1, 3), 128>>>();
    k_scan3<<<dim3(cdiv(N_TX, B), 3), B>>>();
    k_scatter_all<<<cdiv(E_TOT, B), B>>>(eat_s, eat_d, eta_s, eta_d, eaa_s, eaa_d);

    // ---- layers ----
    for (int l = 0; l < 3; l++) {
        if (l > 0) {
            const float* Wa = pW23 + (size_t)(l - 1) * 2 * HID * HID;
            const float* ba = pb23 + (size_t)(l - 1) * 2 * HID;
            k_proj_all<<<PROJ_BLK, B>>>(x_addr, x_tx, 0,
                                        Wa, ba, Wa + HID * HID, ba + HID,
                                        att_src + l * 96, att_dst + l * 96, 8, 3);
        }
        k_agg_all<<<AGG_BLK, B>>>();
        k_semacc<<<dim3(148, 2), B>>>(kW + (size_t)l * HID * HID, kb + l * HID);
        k_attn<<<1, 32>>>(q + l * HID);
    }
    k_lin<<<cdiv(N_ADDR, 8), B>>>(linW, linb, out);
}

// round 13
// speedup vs baseline: 1.1220x; 1.1220x over previous
#include <cuda_runtime.h>
#include <math.h>

#define N_ADDR 150000
#define N_TX   200000
#define HID    32
#define HEADS  4
#define E_AT   1000000
#define E_TA   1000000
#define E_AA   500000
#define E_TOT  (E_AT + E_TA + E_AA)
#define NODES  (N_ADDR + N_TX)
#define W_TOT  (N_TX + 2 * N_ADDR)
#define PROJ_NPB 32
#define SEM_NPB 32

// ---------------- scratch (device globals; no allocations allowed) ----------------
__device__ __align__(16) float g_ha[(size_t)N_ADDR * HID];
__device__ __align__(16) float g_ht[(size_t)N_TX * HID];
__device__ __align__(16) float g_t [(size_t)N_TX * HID];

__device__ __align__(16) float g_oa1[(size_t)N_ADDR * HID];
__device__ __align__(16) float g_oa2[(size_t)N_ADDR * HID];

__device__ __align__(16) float g_asA0[(size_t)N_ADDR * HEADS];
__device__ __align__(16) float g_asA2[(size_t)N_ADDR * HEADS];
__device__ __align__(16) float g_adA1[(size_t)N_ADDR * HEADS];
__device__ __align__(16) float g_adA2[(size_t)N_ADDR * HEADS];
__device__ __align__(16) float g_asT [(size_t)N_TX * HEADS];
__device__ __align__(16) float g_adT [(size_t)N_TX * HEADS];

// CSR structures (built once per launch; topology shared by all 3 layers)
__device__ int g_cnt[3][N_TX];
__device__ int g_off[3][N_TX + 1];
__device__ int g_cur[3][N_TX];
__device__ int g_bsum[3][128];
__device__ int g_csr0[E_AT];
__device__ int g_csr1[E_TA];
__device__ int g_csr2[E_AA];

// zero-initialized at module load; k_attn re-zeroes after each use so every
// layer (and every graph replay) starts from zero.
__device__ unsigned g_gmax[3 * HEADS];
__device__ float g_sem[2 * HID];
__device__ float g_attn[2];

// ---------------- helpers ----------------
__device__ __forceinline__ unsigned fenc(float x) {
    unsigned b = __float_as_uint(x);
    return (b & 0x80000000u) ? ~b : (b | 0x80000000u);
}
__device__ __forceinline__ float fdec(unsigned u) {
    return (u & 0x80000000u) ? __uint_as_float(u & 0x7FFFFFFFu)
                             : __uint_as_float(~u);
}
__device__ __forceinline__ float lrelu(float l) { return l >= 0.f ? l : 0.2f * l; }
__device__ __forceinline__ float tanh_a(float x) {
    float y;
    asm("tanh.approx.f32 %0, %1;" : "=f"(y) : "f"(x));
    return y;
}
static inline int cdiv(int a, int b) { return (a + b - 1) / b; }

// ---------------- CSR build ----------------
__global__ void k_zero_cnt() {
    int i = blockIdx.x * blockDim.x + threadIdx.x;
    if (i < N_TX) g_cnt[0][i] = 0;
    if (i < N_ADDR) { g_cnt[1][i] = 0; g_cnt[2][i] = 0; }
}

__global__ void k_hist_all(const int* __restrict__ d0, const int* __restrict__ d1,
                           const int* __restrict__ d2) {
    int e = blockIdx.x * blockDim.x + threadIdx.x;
    if (e < E_AT) atomicAdd(&g_cnt[0][d0[e]], 1);
    else if (e < E_AT + E_TA) atomicAdd(&g_cnt[1][d1[e - E_AT]], 1);
    else if (e < E_TOT) atomicAdd(&g_cnt[2][d2[e - E_AT - E_TA]], 1);
}

// block-level exclusive scan: 1024 threads x 4 elements; blockIdx.y = relation
__global__ void k_scan1() {
    __shared__ int ws[32];
    int rel = blockIdx.y;
    int N = (rel == 0) ? N_TX : N_ADDR;
    const int* cnt = g_cnt[rel];
    int* off = g_off[rel];
    int t = threadIdx.x, lane = t & 31, wid = t >> 5;
    int base = blockIdx.x * 4096 + t * 4;
    int v0 = (base + 0 < N) ? cnt[base + 0] : 0;
    int v1 = (base + 1 < N) ? cnt[base + 1] : 0;
    int v2 = (base + 2 < N) ? cnt[base + 2] : 0;
    int v3 = (base + 3 < N) ? cnt[base + 3] : 0;
    int tsum = v0 + v1 + v2 + v3;
    int x = tsum;
    for (int o = 1; o < 32; o <<= 1) {
        int y = __shfl_up_sync(0xffffffffu, x, o);
        if (lane >= o) x += y;
    }
    if (lane == 31) ws[wid] = x;
    __syncthreads();
    if (wid == 0) {
        int w = ws[lane];
        for (int o = 1; o < 32; o <<= 1) {
            int y = __shfl_up_sync(0xffffffffu, w, o);
            if (lane >= o) w += y;
        }
        ws[lane] = w;
    }
    __syncthreads();
    int excl = x - tsum + (wid > 0 ? ws[wid - 1] : 0);
    if (base + 0 < N) off[base + 0] = excl;
    if (base + 1 < N) off[base + 1] = excl + v0;
    if (base + 2 < N) off[base + 2] = excl + v0 + v1;
    if (base + 3 < N) off[base + 3] = excl + v0 + v1 + v2;
    if (t == 1023) g_bsum[rel][blockIdx.x] = excl + tsum;
}

__global__ void k_scan2() {
    __shared__ int sh[128];
    int rel = blockIdx.y;
    const int nb = 49;
    int t = threadIdx.x;
    int orig = (t < nb) ? g_bsum[rel][t] : 0;
    sh[t] = orig;
    __syncthreads();
    for (int o = 1; o < 128; o <<= 1) {
        int v = (t >= o) ? sh[t - o] : 0;
        __syncthreads();
        sh[t] += v;
        __syncthreads();
    }
    if (t < nb) g_bsum[rel][t] = sh[t] - orig;
}

__global__ void k_scan3() {
    int rel = blockIdx.y;
    int N = (rel == 0) ? N_TX : N_ADDR;
    int i = blockIdx.x * blockDim.x + threadIdx.x;
    if (i >= N) return;
    int o = g_off[rel][i] + g_bsum[rel][i >> 12];
    g_off[rel][i] = o;
    g_cur[rel][i] = o;
    if (i == N - 1) g_off[rel][N] = o + g_cnt[rel][i];
}

// csr selected in device code (host-side __device__ symbol = wrong address)
__global__ void k_scatter_all(const int* __restrict__ s0, const int* __restrict__ d0,
                              const int* __restrict__ s1, const int* __restrict__ d1,
                              const int* __restrict__ s2, const int* __restrict__ d2) {
    int e = blockIdx.x * blockDim.x + threadIdx.x;
    if (e < E_AT) {
        int p = atomicAdd(&g_cur[0][d0[e]], 1);
        g_csr0[p] = s0[e];
    } else if (e < E_AT + E_TA) {
        int i = e - E_AT;
        int p = atomicAdd(&g_cur[1][d1[i]], 1);
        g_csr1[p] = s1[i];
    } else if (e < E_TOT) {
        int i = e - E_AT - E_TA;
        int p = atomicAdd(&g_cur[2][d2[i]], 1);
        g_csr2[p] = s2[i];
    }
}

// ---------------- per-layer kernels ----------------

// fused: [semantic mix of previous layer (l>0)] + projection (both node types)
// + attention dot products + global alpha_src max (fused k_amax).
// one 32-node tile per block; 4 nodes/warp, 8 lanes/node, lane owns a float4.
__global__ void k_proj_all(const float* __restrict__ xa, const float* __restrict__ xt,
                           int useExt,
                           const float* __restrict__ Wa, const float* __restrict__ ba,
                           const float* __restrict__ Wt, const float* __restrict__ bt,
                           const float* __restrict__ asl, const float* __restrict__ adl,
                           int F4, int f4sh) {
    __shared__ float4 sWa[64 * 8], sWt[64 * 8];
    __shared__ float4 sx[PROJ_NPB * 17];
    __shared__ float4 sba4[8], sbt4[8], sv4[6][8];
    __shared__ unsigned smax[12];
    int tid = threadIdx.x;
    int Wn = (F4 << 2) * 8;
    for (int i = tid; i < Wn; i += blockDim.x) {
        sWa[i] = ((const float4*)Wa)[i];
        sWt[i] = ((const float4*)Wt)[i];
    }
    if (tid < 8) {
        sba4[tid] = ((const float4*)ba)[tid];
        sbt4[tid] = ((const float4*)bt)[tid];
    }
    if (tid < 48) {
        int r = tid >> 3, cc = tid & 7;
        const float* p = (r == 0) ? asl : (r == 1) ? asl + 64 :
                         (r == 2) ? adl + 32 : (r == 3) ? adl + 64 :
                         (r == 4) ? asl + 32 : adl;
        sv4[r][cc] = ((const float4*)p)[cc];
    }
    if (tid < 12) smax[tid] = 0u;

    float a0 = 0.f, a1 = 0.f;
    if (!useExt) { a0 = g_attn[0]; a1 = g_attn[1]; }

    int nbase = blockIdx.x * PROJ_NPB;
    int items = PROJ_NPB << f4sh;
    for (int i = tid; i < items; i += blockDim.x) {
        int row = i >> f4sh, k4 = i & (F4 - 1);
        int node = nbase + row;
        if (node < NODES) {
            bool iA = node < N_ADDR;
            int n = iA ? node : node - N_ADDR;
            float4 v;
            if (useExt) {
                v = ((const float4*)(iA ? xa : xt))[((size_t)n << f4sh) + k4];
            } else if (iA) {
                float4 u = ((const float4*)g_oa1)[(size_t)n * 8 + k4];
                float4 w = ((const float4*)g_oa2)[(size_t)n * 8 + k4];
                v = make_float4(fmaxf(a0 * u.x + a1 * w.x, 0.f),
                                fmaxf(a0 * u.y + a1 * w.y, 0.f),
                                fmaxf(a0 * u.z + a1 * w.z, 0.f),
                                fmaxf(a0 * u.w + a1 * w.w, 0.f));
            } else {
                v = ((const float4*)g_t)[(size_t)n * 8 + k4];
            }
            sx[row * 17 + k4] = v;
        }
    }
    __syncthreads();

    int lane = tid & 31;
    int g = lane >> 3, c4 = lane & 7;
    int lrow = (tid >> 5) * 4 + g;
    int node = nbase + lrow;

    float lm0 = -1e30f, lm1 = -1e30f, lm2 = -1e30f;
    if (node < NODES) {
        bool isA = node < N_ADDR;
        int n = isA ? node : node - N_ADDR;
        const float4* sW = isA ? sWa : sWt;
        float4 acc = isA ? sba4[c4] : sbt4[c4];
        const float4* xr = sx + lrow * 17;
        for (int k4 = 0; k4 < F4; k4++) {
            float4 xv = xr[k4];
            float4 w0 = sW[(4 * k4 + 0) * 8 + c4];
            float4 w1 = sW[(4 * k4 + 1) * 8 + c4];
            float4 w2 = sW[(4 * k4 + 2) * 8 + c4];
            float4 w3 = sW[(4 * k4 + 3) * 8 + c4];
            acc.x += xv.x * w0.x + xv.y * w1.x + xv.z * w2.x + xv.w * w3.x;
            acc.y += xv.x * w0.y + xv.y * w1.y + xv.z * w2.y + xv.w * w3.y;
            acc.z += xv.x * w0.z + xv.y * w1.z + xv.z * w2.z + xv.w * w3.z;
            acc.w += xv.x * w0.w + xv.y * w1.w + xv.z * w2.w + xv.w * w3.w;
        }
        ((float4*)((isA ? g_ha : g_ht) + (size_t)n * HID))[c4] = acc;

        float4 s0 = sv4[isA ? 0 : 4][c4];
        float4 s1 = sv4[isA ? 1 : 5][c4];
        float p0 = acc.x * s0.x + acc.y * s0.y + acc.z * s0.z + acc.w * s0.w;
        float p1 = acc.x * s1.x + acc.y * s1.y + acc.z * s1.z + acc.w * s1.w;
        float p2 = 0.f, p3 = 0.f;
        if (isA) {
            float4 s2 = sv4[2][c4], s3 = sv4[3][c4];
            p2 = acc.x * s2.x + acc.y * s2.y + acc.z * s2.z + acc.w * s2.w;
            p3 = acc.x * s3.x + acc.y * s3.y + acc.z * s3.z + acc.w * s3.w;
        }
        p0 += __shfl_xor_sync(0xffffffffu, p0, 1);
        p1 += __shfl_xor_sync(0xffffffffu, p1, 1);
        p2 += __shfl_xor_sync(0xffffffffu, p2, 1);
        p3 += __shfl_xor_sync(0xffffffffu, p3, 1);
        if ((c4 & 1) == 0) {
            int h = c4 >> 1;
            if (isA) {
                g_asA0[(size_t)n * 4 + h] = p0;
                g_asA2[(size_t)n * 4 + h] = p1;
                g_adA1[(size_t)n * 4 + h] = p2;
                g_adA2[(size_t)n * 4 + h] = p3;
                lm0 = p0; lm2 = p1;
            } else {
                g_asT[(size_t)n * 4 + h] = p0;
                g_adT[(size_t)n * 4 + h] = p1;
                lm1 = p0;
            }
        }
    }

    // reduce alpha_src maxes: smem atomics, then <=12 global atomics per block
    if ((c4 & 1) == 0) {
        int h = c4 >> 1;
        if (lm0 > -1e30f) atomicMax(&smax[0 * 4 + h], fenc(lm0));
        if (lm1 > -1e30f) atomicMax(&smax[1 * 4 + h], fenc(lm1));
        if (lm2 > -1e30f) atomicMax(&smax[2 * 4 + h], fenc(lm2));
    }
    __syncthreads();
    if (tid < 12 && smax[tid] != 0u) atomicMax(&g_gmax[tid], smax[tid]);
}

// fused gather aggregation, all 3 relations. 4 nodes/warp, 8 lanes/node;
// each lane owns one float4 of channels for the whole node -> no cross-lane
// reduction. Group-masked shfl broadcasts prefetched neighbor ids.
// (dynamic inner bound: static unroll with predication regressed in R12)
__global__ void k_agg_all() {
    int warp = blockIdx.x * (blockDim.x >> 5) + (threadIdx.x >> 5);
    int lane = threadIdx.x & 31;
    int g = lane >> 3, c4 = lane & 7, h = c4 >> 1;
    int vn = warp * 4 + g;
    if (vn >= W_TOT) return;
    int rel, node;
    if (vn < N_TX) { rel = 0; node = vn; }
    else if (vn < N_TX + N_ADDR) { rel = 1; node = vn - N_TX; }
    else { rel = 2; node = vn - N_TX - N_ADDR; }

    const int* off; const int* csr; const float* as_; const float* ad_;
    const float* hs; float* outp;
    if (rel == 0)      { off = g_off[0]; csr = g_csr0; as_ = g_asA0; ad_ = g_adT;  hs = g_ha; outp = g_t; }
    else if (rel == 1) { off = g_off[1]; csr = g_csr1; as_ = g_asT;  ad_ = g_adA1; hs = g_ht; outp = g_oa1; }
    else               { off = g_off[2]; csr = g_csr2; as_ = g_asA2; ad_ = g_adA2; hs = g_ha; outp = g_oa2; }

    int start = off[node], end = off[node + 1];
    float4 res = make_float4(0.f, 0.f, 0.f, 0.f);
    if (start < end) {
        float adv = ad_[(size_t)node * 4 + h];
        float m = lrelu(fdec(g_gmax[rel * 4 + h]) + adv);  // >= all edge logits
        unsigned gm = 0xFFu << (g * 8);
        float4 acc = make_float4(0.f, 0.f, 0.f, 0.f);
        float ssum = 0.f;
        for (int base = start; base < end; base += 8) {
            int nrem = min(8, end - base);
            int idx = (c4 < nrem) ? csr[base + c4] : 0;
            for (int j = 0; j < nrem; j++) {
                int s = __shfl_sync(gm, idx, g * 8 + j);
                float a = as_[(size_t)s * 4 + h];
                float w = __expf(lrelu(a + adv) - m);
                float4 f = ((const float4*)(hs + (size_t)s * HID))[c4];
                acc.x += w * f.x; acc.y += w * f.y;
                acc.z += w * f.z; acc.w += w * f.w;
                ssum += w;
            }
        }
        float inv = 1.f / (ssum + 1e-16f);
        res = make_float4(fmaxf(acc.x * inv, 0.f), fmaxf(acc.y * inv, 0.f),
                          fmaxf(acc.z * inv, 0.f), fmaxf(acc.w * inv, 0.f));
    }
    ((float4*)(outp + (size_t)node * HID))[c4] = res;
}

// semantic accumulation, proj-style: 32-node tile staged to smem (coalesced);
// 4 nodes/warp, 8 lanes/node, lane owns a float4 of channels; single-MUFU
// tanh.approx. blockIdx.y = relation.
__global__ void k_semacc(const float* __restrict__ kWl, const float* __restrict__ kbl) {
    int r = blockIdx.y;
    const float* O = (r == 0) ? (const float*)g_oa1 : (const float*)g_oa2;
    __shared__ float4 sW4[32 * 8];
    __shared__ float4 sb4[8];
    __shared__ float4 sx[SEM_NPB * 17];
    __shared__ float red[HID];
    int tid = threadIdx.x;
    for (int i = tid; i < 32 * 8; i += blockDim.x) sW4[i] = ((const float4*)kWl)[i];
    if (tid < 8) sb4[tid] = ((const float4*)kbl)[tid];
    if (tid < HID) red[tid] = 0.f;

    int nbase = blockIdx.x * SEM_NPB;
    for (int i = tid; i < SEM_NPB * 8; i += blockDim.x) {
        int row = i >> 3, k4 = i & 7;
        int n = nbase + row;
        if (n < N_ADDR) sx[row * 17 + k4] = ((const float4*)O)[(size_t)n * 8 + k4];
    }
    __syncthreads();

    int lane = tid & 31, g = lane >> 3, c4 = lane & 7;
    int lrow = (tid >> 5) * 4 + g;
    int node = nbase + lrow;
    float4 t4 = make_float4(0.f, 0.f, 0.f, 0.f);
    if (node < N_ADDR) {
        float4 acc = sb4[c4];
        const float4* xr = sx + lrow * 17;
#pragma unroll
        for (int k4 = 0; k4 < 8; k4++) {
            float4 xv = xr[k4];
            float4 w0 = sW4[(4 * k4 + 0) * 8 + c4];
            float4 w1 = sW4[(4 * k4 + 1) * 8 + c4];
            float4 w2 = sW4[(4 * k4 + 2) * 8 + c4];
            float4 w3 = sW4[(4 * k4 + 3) * 8 + c4];
            acc.x += xv.x * w0.x + xv.y * w1.x + xv.z * w2.x + xv.w * w3.x;
            acc.y += xv.x * w0.y + xv.y * w1.y + xv.z * w2.y + xv.w * w3.y;
            acc.z += xv.x * w0.z + xv.y * w1.z + xv.z * w2.z + xv.w * w3.z;
            acc.w += xv.x * w0.w + xv.y * w1.w + xv.z * w2.w + xv.w * w3.w;
        }
        t4 = make_float4(tanh_a(acc.x), tanh_a(acc.y), tanh_a(acc.z), tanh_a(acc.w));
    }
    // reduce across the 4 groups (lanes c4, c4+8, c4+16, c4+24)
    t4.x += __shfl_xor_sync(0xffffffffu, t4.x, 8);
    t4.y += __shfl_xor_sync(0xffffffffu, t4.y, 8);
    t4.z += __shfl_xor_sync(0xffffffffu, t4.z, 8);
    t4.w += __shfl_xor_sync(0xffffffffu, t4.w, 8);
    t4.x += __shfl_xor_sync(0xffffffffu, t4.x, 16);
    t4.y += __shfl_xor_sync(0xffffffffu, t4.y, 16);
    t4.z += __shfl_xor_sync(0xffffffffu, t4.z, 16);
    t4.w += __shfl_xor_sync(0xffffffffu, t4.w, 16);
    if (lane < 8) {
        atomicAdd(&red[c4 * 4 + 0], t4.x);
        atomicAdd(&red[c4 * 4 + 1], t4.y);
        atomicAdd(&red[c4 * 4 + 2], t4.z);
        atomicAdd(&red[c4 * 4 + 3], t4.w);
    }
    __syncthreads();
    if (tid < HID) atomicAdd(&g_sem[r * HID + tid], red[tid]);
}

// softmax over 2 relation scores; resets g_sem/g_gmax for next layer/replay
__global__ void k_attn(const float* __restrict__ q) {
    int c = threadIdx.x;
    const float inv = 1.0f / (float)N_ADDR;
    float qc = q[c];
    float p0 = g_sem[c] * inv * qc;
    float p1 = g_sem[HID + c] * inv * qc;
    for (int o = 16; o > 0; o >>= 1) {
        p0 += __shfl_xor_sync(0xffffffffu, p0, o);
        p1 += __shfl_xor_sync(0xffffffffu, p1, o);
    }
    if (c == 0) {
        float m = fmaxf(p0, p1);
        float e0 = __expf(p0 - m), e1 = __expf(p1 - m);
        float is = 1.f / (e0 + e1);
        g_attn[0] = e0 * is;
        g_attn[1] = e1 * is;
    }
    __syncwarp();
    g_sem[c] = 0.f;
    g_sem[HID + c] = 0.f;
    if (c < 3 * HEADS) g_gmax[c] = 0u;
}

// final linear with fused semantic mix: warp per node, shfl reduce.
__global__ void k_lin(const float* __restrict__ linW, const float* __restrict__ linb,
                      float* __restrict__ out) {
    int gw = blockIdx.x * (blockDim.x >> 5) + (threadIdx.x >> 5);
    int c = threadIdx.x & 31;
    if (gw >= N_ADDR) return;
    float a0 = g_attn[0], a1 = g_attn[1];
    float v = fmaxf(a0 * g_oa1[(size_t)gw * HID + c] +
                    a1 * g_oa2[(size_t)gw * HID + c], 0.f);
    float s0 = v * linW[c * 2];
    float s1 = v * linW[c * 2 + 1];
#pragma unroll
    for (int o = 16; o > 0; o >>= 1) {
        s0 += __shfl_xor_sync(0xffffffffu, s0, o);
        s1 += __shfl_xor_sync(0xffffffffu, s1, o);
    }
    if (c == 0)
        *(float2*)(out + (size_t)gw * 2) = make_float2(s0 + linb[0], s1 + linb[1]);
}

// ---------------- host ----------------
extern "C" void kernel_launch(void* const* d_in, const int* in_sizes, int n_in,
                              void* d_out, int out_size) {
    const float* x_addr  = (const float*)d_in[0];
    const float* x_tx    = (const float*)d_in[1];
    const int*   eat_s   = (const int*)d_in[2];
    const int*   eat_d   = (const int*)d_in[3];
    const int*   eta_s   = (const int*)d_in[4];
    const int*   eta_d   = (const int*)d_in[5];
    const int*   eaa_s   = (const int*)d_in[6];
    const int*   eaa_d   = (const int*)d_in[7];
    const float* pW1     = (const float*)d_in[8];
    const float* pb1     = (const float*)d_in[9];
    const float* pW23    = (const float*)d_in[10];
    const float* pb23    = (const float*)d_in[11];
    const float* att_src = (const float*)d_in[12];
    const float* att_dst = (const float*)d_in[13];
    const float* kW      = (const float*)d_in[14];
    const float* kb      = (const float*)d_in[15];
    const float* q       = (const float*)d_in[16];
    const float* linW    = (const float*)d_in[17];
    const float* linb    = (const float*)d_in[18];
    float* out = (float*)d_out;

    const int B = 256;
    const int PROJ_BLK = cdiv(NODES, PROJ_NPB);
    const int AGG_BLK = cdiv(W_TOT / 4, 8);   // 4 nodes/warp, 8 warps/block
    const int SEM_BLK = cdiv(N_ADDR, SEM_NPB);

    // ---- CSR build (once); layer-0 proj interleaved (independent) ----
    k_zero_cnt<<<cdiv(N_TX, B), B>>>();
    k_hist_all<<<cdiv(E_TOT, B), B>>>(eat_d, eta_d, eaa_d);
    k_scan1<<<dim3(49, 3), 1024>>>();
    k_proj_all<<<PROJ_BLK, B>>>(x_addr, x_tx, 1,
                                pW1, pb1, pW1 + 64 * HID, pb1 + HID,
                                att_src, att_dst, 16, 4);
    k_scan2<<<dim3(1, 3), 128>>>();
    k_scan3<<<dim3(cdiv(N_TX, B), 3), B>>>();
    k_scatter_all<<<cdiv(E_TOT, B), B>>>(eat_s, eat_d, eta_s, eta_d, eaa_s, eaa_d);

    // ---- layers ----
    for (int l = 0; l < 3; l++) {
        if (l > 0) {
            const float* Wa = pW23 + (size_t)(l - 1) * 2 * HID * HID;
            const float* ba = pb23 + (size_t)(l - 1) * 2 * HID;
            k_proj_all<<<PROJ_BLK, B>>>(x_addr, x_tx, 0,
                                        Wa, ba, Wa + HID * HID, ba + HID,
                                        att_src + l * 96, att_dst + l * 96, 8, 3);
        }
        k_agg_all<<<AGG_BLK, B>>>();
        k_semacc<<<dim3(SEM_BLK, 2), B>>>(kW + (size_t)l * HID * HID, kb + l * HID);
        k_attn<<<1, 32>>>(q + l * HID);
    }
    k_lin<<<cdiv(N_ADDR, 8), B>>>(linW, linb, out);
}